// round 3
// baseline (speedup 1.0000x reference)
#include <cuda_runtime.h>
#include <math.h>

#define T_FRAMES 16384
#define C        7
#define F_DIM    2048
#define LEN_Q    30
#define N_HEADS  4
#define D_FF     64

// ---------------- FC kernel config ----------------
#define FC_FPB   8                       // frames per block
#define RED_FS   577                     // frame stride in red (odd vs 32 banks)
#define RED_SZ   (FC_FPB * RED_FS + 64 * 9)

// ---------------- attention kernel config ----------------
#define TILE     32                      // frames per block
#define ROWS     (TILE + LEN_Q - 1)      // 61
#define NSTR     33                      // N/P row stride -> conflict-free perm

// scratch: per-frame spatial embedding feas = tanh(LF @ W_fc^T), (T, C)
__device__ float g_feas[T_FRAMES * C];

typedef unsigned long long u64;

__device__ __forceinline__ u64 fma2(u64 a, u64 b, u64 c) {
    u64 d;
    asm("fma.rn.f32x2 %0, %1, %2, %3;" : "=l"(d) : "l"(a), "l"(b), "l"(c));
    return d;
}
__device__ __forceinline__ float pairsum(u64 a) {
    const float lo = __uint_as_float((unsigned)(a & 0xffffffffull));
    const float hi = __uint_as_float((unsigned)(a >> 32));
    return lo + hi;
}

// ---------------------------------------------------------------------------
// Kernel A: feas[t][c] = tanh( sum_f LF[t][f] * W_fc[c][f] )
// 256 threads, 8 frames/block. W_fc in registers as packed f32x2 pairs.
// Depth-3 frame prefetch keeps ~24KB/SM of loads in flight.
// ---------------------------------------------------------------------------
__global__ __launch_bounds__(256, 2) void fc_kernel(const float* __restrict__ LF,
                                                    const float* __restrict__ Wfc) {
    __shared__ float red[RED_SZ];

    const int tid  = threadIdx.x;
    const int lane = tid & 31;
    const int warp = tid >> 5;
    const int t0   = blockIdx.x * FC_FPB;

    // W_fc: thread owns 16B chunks tid and tid+256 of every row (as f32x2 pairs)
    ulonglong2 w0[C], w1[C];
#pragma unroll
    for (int c = 0; c < C; ++c) {
        const ulonglong2* wr = reinterpret_cast<const ulonglong2*>(Wfc + c * F_DIM);
        w0[c] = wr[tid];
        w1[c] = wr[tid + 256];
    }

    const ulonglong2* lfb =
        reinterpret_cast<const ulonglong2*>(LF) + (size_t)t0 * 512;

    ulonglong2 A[FC_FPB], B[FC_FPB];
#pragma unroll
    for (int f = 0; f < 3; ++f) {            // prime 3-deep pipeline
        A[f] = lfb[f * 512 + tid];
        B[f] = lfb[f * 512 + tid + 256];
    }

#pragma unroll
    for (int f = 0; f < FC_FPB; ++f) {
        if (f + 3 < FC_FPB) {
            A[f + 3] = lfb[(f + 3) * 512 + tid];
            B[f + 3] = lfb[(f + 3) * 512 + tid + 256];
        }
        float p[C];
#pragma unroll
        for (int c = 0; c < C; ++c) {
            u64 acc = 0ull;                   // (0.f, 0.f)
            acc = fma2(A[f].x, w0[c].x, acc);
            acc = fma2(A[f].y, w0[c].y, acc);
            acc = fma2(B[f].x, w1[c].x, acc);
            acc = fma2(B[f].y, w1[c].y, acc);
            p[c] = pairsum(acc);
        }
        // 2 shuffle rounds -> lanes hold sum over {lane mod 8} group
#pragma unroll
        for (int off = 16; off >= 8; off >>= 1) {
#pragma unroll
            for (int c = 0; c < C; ++c)
                p[c] += __shfl_xor_sync(0xffffffffu, p[c], off);
        }
        if (lane < 8) {
            const int base = f * RED_FS + (warp * 8 + lane) * 9;
#pragma unroll
            for (int c = 0; c < C; ++c) red[base + c] = p[c];
        }
    }
    __syncthreads();

    // final reduce: 4 threads per (frame, channel) output, 224 threads
    if (tid < FC_FPB * C * 4) {
        const int f = tid / (C * 4);
        const int r = tid - f * (C * 4);
        const int c = r >> 2;
        const int q = r & 3;
        float s = 0.f;
        const int base = f * RED_FS + q * 16 * 9 + c;
#pragma unroll
        for (int i = 0; i < 16; ++i) s += red[base + i * 9];
        s += __shfl_xor_sync(0xffffffffu, s, 1);
        s += __shfl_xor_sync(0xffffffffu, s, 2);
        if (q == 0) g_feas[(t0 + f) * C + c] = tanhf(s);
    }
}

// ---------------------------------------------------------------------------
// Kernel B: rank-collapsed windowed MHA + LN1 + FFN + LN2.
// A_h = Wq_h^T Wk_h, B_h = Wo_h Wv_h (7x7/head); N = A*feat, P = B*feat per row.
// 128 threads = 32 frames x 4 heads per block.
// ---------------------------------------------------------------------------
__global__ __launch_bounds__(128) void attn_kernel(
    const float* __restrict__ x,
    const float* __restrict__ Wq,  const float* __restrict__ Wk,
    const float* __restrict__ Wv,  const float* __restrict__ Wo,
    const float* __restrict__ ln1g, const float* __restrict__ ln1b,
    const float* __restrict__ Wff1, const float* __restrict__ Wff2,
    const float* __restrict__ ln2g, const float* __restrict__ ln2b,
    float* __restrict__ out)
{
    __shared__ float s_feats[ROWS][8];     // raw per-frame logits (key/value src)
    __shared__ float s_feas[TILE][8];      // tanh(FC(LF)) (query src)
    __shared__ float sA[N_HEADS][C][8];
    __shared__ float sB[N_HEADS][C][8];
    __shared__ float sN[ROWS * NSTR];
    __shared__ float sP[ROWS * NSTR];

    const int tid = threadIdx.x;
    const int t0  = blockIdx.x * TILE;

    // phase 0: feature rows [t0-29, t0+31] (rows < 0 zero) + feas
    for (int i = tid; i < ROWS * C; i += 128) {
        const int r = i / C, c = i - r * C;
        const int g = t0 - (LEN_Q - 1) + r;
        s_feats[r][c] = (g >= 0) ? x[c * T_FRAMES + g] : 0.f;
    }
    for (int i = tid; i < TILE * C; i += 128) {
        const int r = i / C, c = i - r * C;
        s_feas[r][c] = g_feas[(t0 + r) * C + c];
    }

    // phase 2: per-head 7x7 contractions
    for (int i = tid; i < N_HEADS * C * C; i += 128) {
        const int h = i / (C * C);
        const int rem = i - h * (C * C);
        const int c = rem / C, c2 = rem - c * C;
        const float* wq = Wq + (h * 64) * C + c;
        const float* wk = Wk + (h * 64) * C + c2;
        const float* wo = Wo + c * (N_HEADS * 64) + h * 64;
        const float* wv = Wv + (h * 64) * C + c2;
        float sa = 0.f, sb = 0.f;
#pragma unroll 4
        for (int d = 0; d < 64; ++d) {
            sa = fmaf(wq[d * C], wk[d * C], sa);
            sb = fmaf(wo[d],     wv[d * C], sb);
        }
        sA[h][c][c2] = sa;
        sB[h][c][c2] = sb;
    }
    __syncthreads();

    // phase 3: N[r,h,c], P[r,h,c]
    for (int i = tid; i < ROWS * N_HEADS * C; i += 128) {
        const int r = i / (N_HEADS * C);
        const int j = i - r * (N_HEADS * C);
        const int h = j / C, c = j - h * C;
        float sn = 0.f, sp = 0.f;
#pragma unroll
        for (int c2 = 0; c2 < C; ++c2) {
            const float fv = s_feats[r][c2];
            sn = fmaf(sA[h][c][c2], fv, sn);
            sp = fmaf(sB[h][c][c2], fv, sp);
        }
        sN[r * NSTR + h * 8 + c] = sn;
        sP[r * NSTR + h * 8 + c] = sp;
    }
    __syncthreads();

    // phase 4: attention + LN1 + FFN + LN2 (thread = frame x head)
    const int f = tid >> 2;
    const int h = tid & 3;
    const int t = t0 + f;

    float ff[C];
#pragma unroll
    for (int c = 0; c < C; ++c) ff[c] = s_feas[f][c];

    float sc[LEN_Q];
    const float* nb = sN + f * NSTR + h * 8;
#pragma unroll
    for (int l = 0; l < LEN_Q; ++l) {
        const float* nr = nb + l * NSTR;
        float s = ff[0] * nr[0];
#pragma unroll
        for (int c = 1; c < C; ++c) s = fmaf(ff[c], nr[c], s);
        sc[l] = s * 0.125f;
    }

    float mx = sc[0];
#pragma unroll
    for (int l = 1; l < LEN_Q; ++l) mx = fmaxf(mx, sc[l]);
    float den = 0.f;
#pragma unroll
    for (int l = 0; l < LEN_Q; ++l) { sc[l] = __expf(sc[l] - mx); den += sc[l]; }
    const float inv = 1.f / den;
#pragma unroll
    for (int l = 0; l < LEN_Q; ++l) sc[l] *= inv;

    float o[C];
#pragma unroll
    for (int c = 0; c < C; ++c) o[c] = 0.f;
    const float* pb = sP + f * NSTR + h * 8;
#pragma unroll
    for (int l = 0; l < LEN_Q; ++l) {
        const float w = sc[l];
        const float* pr = pb + l * NSTR;
#pragma unroll
        for (int c = 0; c < C; ++c) o[c] = fmaf(w, pr[c], o[c]);
    }
#pragma unroll
    for (int c = 0; c < C; ++c) {
        o[c] += __shfl_xor_sync(0xffffffffu, o[c], 1);
        o[c] += __shfl_xor_sync(0xffffffffu, o[c], 2);
    }

    // LN1 (all 4 lanes so FFN splits 4 ways)
    float res[C];
    float mu = 0.f;
#pragma unroll
    for (int c = 0; c < C; ++c) { res[c] = o[c] + ff[c]; mu += res[c]; }
    mu *= (1.f / C);
    float var = 0.f;
#pragma unroll
    for (int c = 0; c < C; ++c) { const float dv = res[c] - mu; var += dv * dv; }
    var *= (1.f / C);
    float rs = rsqrtf(var + 1e-5f);
#pragma unroll
    for (int c = 0; c < C; ++c) res[c] = (res[c] - mu) * rs * ln1g[c] + ln1b[c];

    // FFN: each lane handles 16 of 64 hidden units
    float y[C];
#pragma unroll
    for (int c = 0; c < C; ++c) y[c] = 0.f;
    const int j0 = h * 16;
#pragma unroll
    for (int jj = 0; jj < 16; ++jj) {
        const int j = j0 + jj;
        float a = 0.f;
#pragma unroll
        for (int c = 0; c < C; ++c) a = fmaf(res[c], Wff1[j * C + c], a);
        a = fmaxf(a, 0.f);
#pragma unroll
        for (int c = 0; c < C; ++c) y[c] = fmaf(a, Wff2[c * D_FF + j], y[c]);
    }
#pragma unroll
    for (int c = 0; c < C; ++c) {
        y[c] += __shfl_xor_sync(0xffffffffu, y[c], 1);
        y[c] += __shfl_xor_sync(0xffffffffu, y[c], 2);
    }

    if (h == 0) {
        float z[C];
        mu = 0.f;
#pragma unroll
        for (int c = 0; c < C; ++c) { z[c] = y[c] + res[c]; mu += z[c]; }
        mu *= (1.f / C);
        var = 0.f;
#pragma unroll
        for (int c = 0; c < C; ++c) { const float dv = z[c] - mu; var += dv * dv; }
        var *= (1.f / C);
        rs = rsqrtf(var + 1e-5f);
#pragma unroll
        for (int c = 0; c < C; ++c)
            out[t * C + c] = (z[c] - mu) * rs * ln2g[c] + ln2b[c];
    }
}

// ---------------------------------------------------------------------------
extern "C" void kernel_launch(void* const* d_in, const int* in_sizes, int n_in,
                              void* d_out, int out_size) {
    const float* x    = (const float*)d_in[0];
    const float* LF   = (const float*)d_in[1];
    const float* Wfc  = (const float*)d_in[2];
    const float* Wq   = (const float*)d_in[3];
    const float* Wk   = (const float*)d_in[4];
    const float* Wv   = (const float*)d_in[5];
    const float* Wo   = (const float*)d_in[6];
    const float* ln1g = (const float*)d_in[7];
    const float* ln1b = (const float*)d_in[8];
    const float* Wff1 = (const float*)d_in[9];
    const float* Wff2 = (const float*)d_in[10];
    const float* ln2g = (const float*)d_in[11];
    const float* ln2b = (const float*)d_in[12];
    float* out = (float*)d_out;

    fc_kernel<<<T_FRAMES / FC_FPB, 256>>>(LF, Wfc);
    attn_kernel<<<T_FRAMES / TILE, 128>>>(
        x, Wq, Wk, Wv, Wo, ln1g, ln1b, Wff1, Wff2, ln2g, ln2b, out);
}

// round 4
// speedup vs baseline: 1.2767x; 1.2767x over previous
#include <cuda_runtime.h>
#include <math.h>

#define T_FRAMES 16384
#define C        7
#define F_DIM    2048
#define LEN_Q    30
#define N_HEADS  4
#define D_FF     64

// ---------------- FC kernel config ----------------
#define FC_FPB   32                      // frames per block
#define RED_FS   577                     // per-frame stride in red (odd)
#define RED_F    (FC_FPB * RED_FS)       // 18464 floats = 73.86 KB

// ---------------- attention kernel config ----------------
#define TILE     32                      // frames per block
#define ROWS     (TILE + LEN_Q - 1)      // 61
#define NSTR     33                      // N/P row stride -> conflict-free perm

// scratch globals
__device__ float g_feas[T_FRAMES * C];       // tanh(LF @ Wfc^T)
__device__ float g_A[N_HEADS][C][8];         // A_h = Wq_h^T Wk_h
__device__ float g_B[N_HEADS][C][8];         // B_h = Wo_h  Wv_h

typedef unsigned long long u64;

__device__ __forceinline__ u64 fma2(u64 a, u64 b, u64 c) {
    u64 d;
    asm("fma.rn.f32x2 %0, %1, %2, %3;" : "=l"(d) : "l"(a), "l"(b), "l"(c));
    return d;
}
__device__ __forceinline__ float pairsum(u64 a) {
    const float lo = __uint_as_float((unsigned)(a & 0xffffffffull));
    const float hi = __uint_as_float((unsigned)(a >> 32));
    return lo + hi;
}

extern __shared__ float red[];

// ---------------------------------------------------------------------------
// Kernel A: feas[t][c] = tanh( sum_f LF[t][f] * W_fc[c][f] )
// 256 threads, 32 frames/block. W_fc in registers (packed f32x2).
// Register prefetch ring depth 4 (3 frames ahead). One barrier per CTA.
// Block 0 additionally computes the rank-collapsed A/B 7x7 matrices.
// ---------------------------------------------------------------------------
__global__ __launch_bounds__(256, 2) void fc_kernel(
    const float* __restrict__ LF,  const float* __restrict__ Wfc,
    const float* __restrict__ Wq,  const float* __restrict__ Wk,
    const float* __restrict__ Wv,  const float* __restrict__ Wo)
{
    const int tid  = threadIdx.x;
    const int lane = tid & 31;
    const int warp = tid >> 5;
    const int t0   = blockIdx.x * FC_FPB;

    // W_fc: thread owns 16B chunks tid and tid+256 of every row (f32x2 pairs)
    ulonglong2 w0[C], w1[C];
#pragma unroll
    for (int c = 0; c < C; ++c) {
        const ulonglong2* wr = reinterpret_cast<const ulonglong2*>(Wfc + c * F_DIM);
        w0[c] = wr[tid];
        w1[c] = wr[tid + 256];
    }

    const ulonglong2* lfb =
        reinterpret_cast<const ulonglong2*>(LF) + (size_t)t0 * 512;

    ulonglong2 A[4], B[4];                     // register ring, depth 4
#pragma unroll
    for (int f = 0; f < 3; ++f) {
        A[f] = lfb[f * 512 + tid];
        B[f] = lfb[f * 512 + tid + 256];
    }

#pragma unroll 4
    for (int f = 0; f < FC_FPB; ++f) {
        if (f < FC_FPB - 3) {
            A[(f + 3) & 3] = lfb[(f + 3) * 512 + tid];
            B[(f + 3) & 3] = lfb[(f + 3) * 512 + tid + 256];
        }
        const ulonglong2 a = A[f & 3];
        const ulonglong2 b = B[f & 3];
        float p[C];
#pragma unroll
        for (int c = 0; c < C; ++c) {
            u64 acc = 0ull;
            acc = fma2(a.x, w0[c].x, acc);
            acc = fma2(a.y, w0[c].y, acc);
            acc = fma2(b.x, w1[c].x, acc);
            acc = fma2(b.y, w1[c].y, acc);
            p[c] = pairsum(acc);
        }
        // 2 shuffle rounds -> every lane holds the sum of its mod-8 class
#pragma unroll
        for (int off = 16; off >= 8; off >>= 1) {
#pragma unroll
            for (int c = 0; c < C; ++c)
                p[c] += __shfl_xor_sync(0xffffffffu, p[c], off);
        }
        if (lane < 8) {
            const int base = f * RED_FS + (warp * 8 + lane) * 9;
#pragma unroll
            for (int c = 0; c < C; ++c) red[base + c] = p[c];
        }
    }
    __syncthreads();

    // final reduce: 1 thread per (frame, channel) output, 224 threads
    if (tid < FC_FPB * C) {
        const int f = tid / C;
        const int c = tid - f * C;
        float s = 0.f;
        const int base = f * RED_FS + c;
#pragma unroll
        for (int i = 0; i < 64; ++i) s += red[base + i * 9];
        g_feas[(t0 + f) * C + c] = tanhf(s);
    }

    // block 0 tail: per-head 7x7 contractions A_h, B_h (once for the grid)
    if (blockIdx.x == 0 && tid < N_HEADS * C * C) {
        const int h = tid / (C * C);
        const int rem = tid - h * (C * C);
        const int c = rem / C, c2 = rem - c * C;
        const float* wq = Wq + (h * 64) * C + c;
        const float* wk = Wk + (h * 64) * C + c2;
        const float* wo = Wo + c * (N_HEADS * 64) + h * 64;
        const float* wv = Wv + (h * 64) * C + c2;
        float sa = 0.f, sb = 0.f;
#pragma unroll 4
        for (int d = 0; d < 64; ++d) {
            sa = fmaf(wq[d * C], wk[d * C], sa);
            sb = fmaf(wo[d],     wv[d * C], sb);
        }
        g_A[h][c][c2] = sa;
        g_B[h][c][c2] = sb;
    }
}

// ---------------------------------------------------------------------------
// Kernel B: rank-collapsed windowed MHA + LN1 + FFN + LN2.
// 128 threads = 32 frames x 4 heads per block. No heavy global phases:
// A/B come precomputed from g_A/g_B; FFN weights staged in smem.
// ---------------------------------------------------------------------------
__global__ __launch_bounds__(128) void attn_kernel(
    const float* __restrict__ x,
    const float* __restrict__ ln1g, const float* __restrict__ ln1b,
    const float* __restrict__ Wff1, const float* __restrict__ Wff2,
    const float* __restrict__ ln2g, const float* __restrict__ ln2b,
    float* __restrict__ out)
{
    __shared__ float s_feats[ROWS][8];
    __shared__ float s_feas[TILE][8];
    __shared__ float sA[N_HEADS * C * 8];
    __shared__ float sB[N_HEADS * C * 8];
    __shared__ float sN[ROWS * NSTR];
    __shared__ float sP[ROWS * NSTR];
    __shared__ float sF1[D_FF * 9];        // Wff1[j][c] at j*9+c
    __shared__ float sF2[C * 65];          // Wff2[c][j] at c*65+j

    const int tid = threadIdx.x;
    const int t0  = blockIdx.x * TILE;

    // stage small operands
    for (int i = tid; i < N_HEADS * C * 8; i += 128) {
        sA[i] = (&g_A[0][0][0])[i];
        sB[i] = (&g_B[0][0][0])[i];
    }
    for (int i = tid; i < D_FF * C; i += 128) {
        const int j = i / C, c = i - j * C;
        sF1[j * 9 + c] = Wff1[i];
    }
    for (int i = tid; i < C * D_FF; i += 128) {
        const int c = i / D_FF, j = i - c * D_FF;
        sF2[c * 65 + j] = Wff2[i];
    }
    for (int i = tid; i < ROWS * C; i += 128) {
        const int r = i / C, c = i - r * C;
        const int g = t0 - (LEN_Q - 1) + r;
        s_feats[r][c] = (g >= 0) ? x[c * T_FRAMES + g] : 0.f;
    }
    for (int i = tid; i < TILE * C; i += 128) {
        const int r = i / C, c = i - r * C;
        s_feas[r][c] = g_feas[(t0 + r) * C + c];
    }
    __syncthreads();

    // N[r,h,c] = (A_h feat_r)[c],  P[r,h,c] = (B_h feat_r)[c]
    for (int i = tid; i < ROWS * N_HEADS * C; i += 128) {
        const int r = i / (N_HEADS * C);
        const int j = i - r * (N_HEADS * C);
        const int h = j / C, c = j - h * C;
        float sn = 0.f, sp = 0.f;
        const int ab = h * 56 + c * 8;
#pragma unroll
        for (int c2 = 0; c2 < C; ++c2) {
            const float fv = s_feats[r][c2];
            sn = fmaf(sA[ab + c2], fv, sn);
            sp = fmaf(sB[ab + c2], fv, sp);
        }
        sN[r * NSTR + h * 8 + c] = sn;
        sP[r * NSTR + h * 8 + c] = sp;
    }
    __syncthreads();

    // attention + LN1 + FFN + LN2 (thread = frame x head)
    const int f = tid >> 2;
    const int h = tid & 3;
    const int t = t0 + f;

    float ff[C];
#pragma unroll
    for (int c = 0; c < C; ++c) ff[c] = s_feas[f][c];

    float sc[LEN_Q];
    const float* nb = sN + f * NSTR + h * 8;
#pragma unroll
    for (int l = 0; l < LEN_Q; ++l) {
        const float* nr = nb + l * NSTR;
        float s = ff[0] * nr[0];
#pragma unroll
        for (int c = 1; c < C; ++c) s = fmaf(ff[c], nr[c], s);
        sc[l] = s * 0.125f;
    }

    float mx = sc[0];
#pragma unroll
    for (int l = 1; l < LEN_Q; ++l) mx = fmaxf(mx, sc[l]);
    float den = 0.f;
#pragma unroll
    for (int l = 0; l < LEN_Q; ++l) { sc[l] = __expf(sc[l] - mx); den += sc[l]; }
    const float inv = 1.f / den;
#pragma unroll
    for (int l = 0; l < LEN_Q; ++l) sc[l] *= inv;

    float o[C];
#pragma unroll
    for (int c = 0; c < C; ++c) o[c] = 0.f;
    const float* pb = sP + f * NSTR + h * 8;
#pragma unroll
    for (int l = 0; l < LEN_Q; ++l) {
        const float w = sc[l];
        const float* pr = pb + l * NSTR;
#pragma unroll
        for (int c = 0; c < C; ++c) o[c] = fmaf(w, pr[c], o[c]);
    }
#pragma unroll
    for (int c = 0; c < C; ++c) {
        o[c] += __shfl_xor_sync(0xffffffffu, o[c], 1);
        o[c] += __shfl_xor_sync(0xffffffffu, o[c], 2);
    }

    // LN1 (all 4 lanes so FFN splits 4 ways)
    float res[C];
    float mu = 0.f;
#pragma unroll
    for (int c = 0; c < C; ++c) { res[c] = o[c] + ff[c]; mu += res[c]; }
    mu *= (1.f / C);
    float var = 0.f;
#pragma unroll
    for (int c = 0; c < C; ++c) { const float dv = res[c] - mu; var += dv * dv; }
    var *= (1.f / C);
    float rs = rsqrtf(var + 1e-5f);
#pragma unroll
    for (int c = 0; c < C; ++c) res[c] = (res[c] - mu) * rs * ln1g[c] + ln1b[c];

    // FFN: each lane handles 16 of 64 hidden units
    float y[C];
#pragma unroll
    for (int c = 0; c < C; ++c) y[c] = 0.f;
    const int j0 = h * 16;
#pragma unroll
    for (int jj = 0; jj < 16; ++jj) {
        const int j = j0 + jj;
        float a = 0.f;
#pragma unroll
        for (int c = 0; c < C; ++c) a = fmaf(res[c], sF1[j * 9 + c], a);
        a = fmaxf(a, 0.f);
#pragma unroll
        for (int c = 0; c < C; ++c) y[c] = fmaf(a, sF2[c * 65 + j], y[c]);
    }
#pragma unroll
    for (int c = 0; c < C; ++c) {
        y[c] += __shfl_xor_sync(0xffffffffu, y[c], 1);
        y[c] += __shfl_xor_sync(0xffffffffu, y[c], 2);
    }

    if (h == 0) {
        float z[C];
        mu = 0.f;
#pragma unroll
        for (int c = 0; c < C; ++c) { z[c] = y[c] + res[c]; mu += z[c]; }
        mu *= (1.f / C);
        var = 0.f;
#pragma unroll
        for (int c = 0; c < C; ++c) { const float dv = z[c] - mu; var += dv * dv; }
        var *= (1.f / C);
        rs = rsqrtf(var + 1e-5f);
#pragma unroll
        for (int c = 0; c < C; ++c)
            out[t * C + c] = (z[c] - mu) * rs * ln2g[c] + ln2b[c];
    }
}

// ---------------------------------------------------------------------------
extern "C" void kernel_launch(void* const* d_in, const int* in_sizes, int n_in,
                              void* d_out, int out_size) {
    const float* x    = (const float*)d_in[0];
    const float* LF   = (const float*)d_in[1];
    const float* Wfc  = (const float*)d_in[2];
    const float* Wq   = (const float*)d_in[3];
    const float* Wk   = (const float*)d_in[4];
    const float* Wv   = (const float*)d_in[5];
    const float* Wo   = (const float*)d_in[6];
    const float* ln1g = (const float*)d_in[7];
    const float* ln1b = (const float*)d_in[8];
    const float* Wff1 = (const float*)d_in[9];
    const float* Wff2 = (const float*)d_in[10];
    const float* ln2g = (const float*)d_in[11];
    const float* ln2b = (const float*)d_in[12];
    float* out = (float*)d_out;

    const int red_bytes = RED_F * (int)sizeof(float);   // 73856
    cudaFuncSetAttribute(fc_kernel,
                         cudaFuncAttributeMaxDynamicSharedMemorySize, red_bytes);

    fc_kernel<<<T_FRAMES / FC_FPB, 256, red_bytes>>>(LF, Wfc, Wq, Wk, Wv, Wo);
    attn_kernel<<<T_FRAMES / TILE, 128>>>(
        x, ln1g, ln1b, Wff1, Wff2, ln2g, ln2b, out);
}

// round 5
// speedup vs baseline: 1.3993x; 1.0961x over previous
#include <cuda_runtime.h>
#include <math.h>

#define T_FRAMES 16384
#define C        7
#define F_DIM    2048
#define LEN_Q    30
#define N_HEADS  4
#define D_FF     64

#define FPB      64                      // frames per block
#define ROWS     (FPB + LEN_Q - 1)       // 93 feature rows per tile
#define NSTR     33                      // N/P row stride -> conflict-free perm
#define RED_FS   292                     // per-frame stride in red (32*9+4)
#define RED_F    (FPB * RED_FS)          // 18688 floats = 74.75 KB
#define NP_F     (ROWS * NSTR)           // 3069

typedef unsigned long long u64;

__device__ __forceinline__ u64 fma2(u64 a, u64 b, u64 c) {
    u64 d;
    asm("fma.rn.f32x2 %0, %1, %2, %3;" : "=l"(d) : "l"(a), "l"(b), "l"(c));
    return d;
}
__device__ __forceinline__ float pairsum(u64 a) {
    const float lo = __uint_as_float((unsigned)(a & 0xffffffffull));
    const float hi = __uint_as_float((unsigned)(a >> 32));
    return lo + hi;
}

extern __shared__ float dyn[];   // red (74.75KB), later aliased as sN/sP

__global__ __launch_bounds__(256, 2) void fused_kernel(
    const float* __restrict__ x,    const float* __restrict__ LF,
    const float* __restrict__ Wfc,  const float* __restrict__ Wq,
    const float* __restrict__ Wk,   const float* __restrict__ Wv,
    const float* __restrict__ Wo,
    const float* __restrict__ ln1g, const float* __restrict__ ln1b,
    const float* __restrict__ Wff1, const float* __restrict__ Wff2,
    const float* __restrict__ ln2g, const float* __restrict__ ln2b,
    float* __restrict__ out)
{
    __shared__ float s_feats[ROWS][8];   // raw per-frame logits (key/value src)
    __shared__ float s_feas[FPB][8];     // tanh(FC(LF)) (query src)
    __shared__ float sA[N_HEADS][C][8];  // A_h = Wq_h^T Wk_h
    __shared__ float sB[N_HEADS][C][8];  // B_h = Wo_h  Wv_h
    __shared__ float sF1[D_FF * 9];      // Wff1[j][c] at j*9+c
    __shared__ float sF2[C * 65];        // Wff2[c][j] at c*65+j

    float* red = dyn;
    float* sN  = dyn;                    // aliased after barrier2
    float* sP  = dyn + NP_F;

    const int tid  = threadIdx.x;
    const int lane = tid & 31;
    const int warp = tid >> 5;
    const int t0   = blockIdx.x * FPB;

    // ---- early staging (latency hidden under FC stream) ----
    for (int i = tid; i < ROWS * C; i += 256) {
        const int r = i / C, c = i - r * C;
        const int g = t0 - (LEN_Q - 1) + r;
        s_feats[r][c] = (g >= 0) ? x[c * T_FRAMES + g] : 0.f;
    }
    for (int i = tid; i < D_FF * C; i += 256) {
        const int j = i / C, c = i - j * C;
        sF1[j * 9 + c] = Wff1[i];
    }
    for (int i = tid; i < C * D_FF; i += 256) {
        const int c = i / D_FF, j = i - c * D_FF;
        sF2[c * 65 + j] = Wff2[i];
    }

    // ---- FC: W_fc in registers (packed f32x2 pairs) ----
    ulonglong2 w0[C], w1[C];
#pragma unroll
    for (int c = 0; c < C; ++c) {
        const ulonglong2* wr = reinterpret_cast<const ulonglong2*>(Wfc + c * F_DIM);
        w0[c] = wr[tid];
        w1[c] = wr[tid + 256];
    }

    const ulonglong2* lfb =
        reinterpret_cast<const ulonglong2*>(LF) + (size_t)t0 * 512;

    ulonglong2 A[4], B[4];               // register prefetch ring, depth 4
#pragma unroll
    for (int f = 0; f < 3; ++f) {
        A[f] = lfb[f * 512 + tid];
        B[f] = lfb[f * 512 + tid + 256];
    }

#pragma unroll 4
    for (int f = 0; f < FPB; ++f) {
        if (f < FPB - 3) {
            A[(f + 3) & 3] = lfb[(f + 3) * 512 + tid];
            B[(f + 3) & 3] = lfb[(f + 3) * 512 + tid + 256];
        }
        const ulonglong2 a = A[f & 3];
        const ulonglong2 b = B[f & 3];
        float p[C];
#pragma unroll
        for (int c = 0; c < C; ++c) {
            u64 acc = 0ull;
            acc = fma2(a.x, w0[c].x, acc);
            acc = fma2(a.y, w0[c].y, acc);
            acc = fma2(b.x, w1[c].x, acc);
            acc = fma2(b.y, w1[c].y, acc);
            p[c] = pairsum(acc);
        }
        // 3 shuffle rounds -> lanes 0..3 hold mod-4 class partials
#pragma unroll
        for (int off = 16; off >= 4; off >>= 1) {
#pragma unroll
            for (int c = 0; c < C; ++c)
                p[c] += __shfl_xor_sync(0xffffffffu, p[c], off);
        }
        if (lane < 4) {
            const int base = f * RED_FS + (warp * 4 + lane) * 9;
#pragma unroll
            for (int c = 0; c < C; ++c) red[base + c] = p[c];
        }
    }
    __syncthreads();                                  // barrier 1

    // ---- feas final reduce + tanh ----
    for (int i = tid; i < FPB * C; i += 256) {
        const int f = i / C, c = i - f * C;
        float s = 0.f;
        const int base = f * RED_FS + c;
#pragma unroll
        for (int j = 0; j < 32; ++j) s += red[base + j * 9];
        s_feas[f][c] = tanhf(s);
    }

    // ---- per-head 7x7 contractions (once per block) ----
    if (tid < N_HEADS * C * C) {
        const int h = tid / (C * C);
        const int rem = tid - h * (C * C);
        const int c = rem / C, c2 = rem - c * C;
        const float* wq = Wq + (h * 64) * C + c;
        const float* wk = Wk + (h * 64) * C + c2;
        const float* wo = Wo + c * (N_HEADS * 64) + h * 64;
        const float* wv = Wv + (h * 64) * C + c2;
        float sa = 0.f, sb = 0.f;
#pragma unroll 8
        for (int d = 0; d < 64; ++d) {
            sa = fmaf(wq[d * C], wk[d * C], sa);
            sb = fmaf(wo[d],     wv[d * C], sb);
        }
        sA[h][c][c2] = sa;
        sB[h][c][c2] = sb;
    }
    __syncthreads();                                  // barrier 2 (red dead now)

    // ---- N[r,h,c] = (A_h feat_r)[c],  P[r,h,c] = (B_h feat_r)[c] ----
    for (int i = tid; i < ROWS * N_HEADS * C; i += 256) {
        const int r = i / (N_HEADS * C);
        const int j = i - r * (N_HEADS * C);
        const int h = j / C, c = j - h * C;
        float sn = 0.f, sp = 0.f;
#pragma unroll
        for (int c2 = 0; c2 < C; ++c2) {
            const float fv = s_feats[r][c2];
            sn = fmaf(sA[h][c][c2], fv, sn);
            sp = fmaf(sB[h][c][c2], fv, sp);
        }
        sN[r * NSTR + h * 8 + c] = sn;
        sP[r * NSTR + h * 8 + c] = sp;
    }
    __syncthreads();                                  // barrier 3

    // ---- attention + LN1 + FFN + LN2 (thread = frame x head) ----
    const int f = tid >> 2;
    const int h = tid & 3;
    const int t = t0 + f;

    float ff[C];
#pragma unroll
    for (int c = 0; c < C; ++c) ff[c] = s_feas[f][c];

    float sc[LEN_Q];
    const float* nb = sN + f * NSTR + h * 8;
#pragma unroll
    for (int l = 0; l < LEN_Q; ++l) {
        const float* nr = nb + l * NSTR;
        float s = ff[0] * nr[0];
#pragma unroll
        for (int c = 1; c < C; ++c) s = fmaf(ff[c], nr[c], s);
        sc[l] = s * 0.125f;
    }

    float mx = sc[0];
#pragma unroll
    for (int l = 1; l < LEN_Q; ++l) mx = fmaxf(mx, sc[l]);
    float den = 0.f;
#pragma unroll
    for (int l = 0; l < LEN_Q; ++l) { sc[l] = __expf(sc[l] - mx); den += sc[l]; }
    const float inv = 1.f / den;
#pragma unroll
    for (int l = 0; l < LEN_Q; ++l) sc[l] *= inv;

    float o[C];
#pragma unroll
    for (int c = 0; c < C; ++c) o[c] = 0.f;
    const float* pb = sP + f * NSTR + h * 8;
#pragma unroll
    for (int l = 0; l < LEN_Q; ++l) {
        const float w = sc[l];
        const float* pr = pb + l * NSTR;
#pragma unroll
        for (int c = 0; c < C; ++c) o[c] = fmaf(w, pr[c], o[c]);
    }
#pragma unroll
    for (int c = 0; c < C; ++c) {
        o[c] += __shfl_xor_sync(0xffffffffu, o[c], 1);
        o[c] += __shfl_xor_sync(0xffffffffu, o[c], 2);
    }

    // LN1 (all 4 lanes so FFN splits 4 ways)
    float res[C];
    float mu = 0.f;
#pragma unroll
    for (int c = 0; c < C; ++c) { res[c] = o[c] + ff[c]; mu += res[c]; }
    mu *= (1.f / C);
    float var = 0.f;
#pragma unroll
    for (int c = 0; c < C; ++c) { const float dv = res[c] - mu; var += dv * dv; }
    var *= (1.f / C);
    float rs = rsqrtf(var + 1e-5f);
#pragma unroll
    for (int c = 0; c < C; ++c) res[c] = (res[c] - mu) * rs * ln1g[c] + ln1b[c];

    // FFN: each lane handles 16 of 64 hidden units
    float y[C];
#pragma unroll
    for (int c = 0; c < C; ++c) y[c] = 0.f;
    const int j0 = h * 16;
#pragma unroll
    for (int jj = 0; jj < 16; ++jj) {
        const int j = j0 + jj;
        float a = 0.f;
#pragma unroll
        for (int c = 0; c < C; ++c) a = fmaf(res[c], sF1[j * 9 + c], a);
        a = fmaxf(a, 0.f);
#pragma unroll
        for (int c = 0; c < C; ++c) y[c] = fmaf(a, sF2[c * 65 + j], y[c]);
    }
#pragma unroll
    for (int c = 0; c < C; ++c) {
        y[c] += __shfl_xor_sync(0xffffffffu, y[c], 1);
        y[c] += __shfl_xor_sync(0xffffffffu, y[c], 2);
    }

    if (h == 0) {
        float z[C];
        mu = 0.f;
#pragma unroll
        for (int c = 0; c < C; ++c) { z[c] = y[c] + res[c]; mu += z[c]; }
        mu *= (1.f / C);
        var = 0.f;
#pragma unroll
        for (int c = 0; c < C; ++c) { const float dv = z[c] - mu; var += dv * dv; }
        var *= (1.f / C);
        rs = rsqrtf(var + 1e-5f);
#pragma unroll
        for (int c = 0; c < C; ++c)
            out[t * C + c] = (z[c] - mu) * rs * ln2g[c] + ln2b[c];
    }
}

// ---------------------------------------------------------------------------
extern "C" void kernel_launch(void* const* d_in, const int* in_sizes, int n_in,
                              void* d_out, int out_size) {
    const float* x    = (const float*)d_in[0];
    const float* LF   = (const float*)d_in[1];
    const float* Wfc  = (const float*)d_in[2];
    const float* Wq   = (const float*)d_in[3];
    const float* Wk   = (const float*)d_in[4];
    const float* Wv   = (const float*)d_in[5];
    const float* Wo   = (const float*)d_in[6];
    const float* ln1g = (const float*)d_in[7];
    const float* ln1b = (const float*)d_in[8];
    const float* Wff1 = (const float*)d_in[9];
    const float* Wff2 = (const float*)d_in[10];
    const float* ln2g = (const float*)d_in[11];
    const float* ln2b = (const float*)d_in[12];
    float* out = (float*)d_out;

    const int dyn_bytes = RED_F * (int)sizeof(float);   // 74752
    cudaFuncSetAttribute(fused_kernel,
                         cudaFuncAttributeMaxDynamicSharedMemorySize, dyn_bytes);

    fused_kernel<<<T_FRAMES / FPB, 256, dyn_bytes>>>(
        x, LF, Wfc, Wq, Wk, Wv, Wo, ln1g, ln1b,
        Wff1, Wff2, ln2g, ln2b, out);
}